// round 6
// baseline (speedup 1.0000x reference)
#include <cuda_runtime.h>
#include <cuda_bf16.h>
#include <cuda_fp16.h>
#include <math.h>
#include <stdint.h>

// ---------------- problem constants ----------------
#define B   512
#define D   256
#define C   100000
#define CPAD 100096              // padded to multiple of 256
#define KA   512                 // A K-extent: [fhi | flo] fp16
#define KB   256                 // B K-extent: fp16(W)

#define S_SCALE   30.0f
#define COS_M     0.8775825618903728f
#define SIN_M     0.479425538604203f
#define THRESH   (-0.8775825618903728f)
#define MM_CONST  0.2397127693021015f
#define EPS_N     1e-12f

#define PRED_ELEMS   ((size_t)B * C)
#define W_ELEMS      ((size_t)C * D)

// ---------------- device scratch ----------------
__device__ float g_fnorm[B * D];
__device__ float g_tl[B];
__device__ float g_ctm[B];
__device__ float g_ftl[B];
__device__ float g_tnew;
__device__ int   g_counts[C];    // invariant: all-zero at kernel_launch entry
__device__ int   g_targets[B];
__device__ __half g_A[B * KA];                    // [512, 512] = [fhi | flo]
__device__ __half g_Bw[(size_t)CPAD * KB];        // [100096, 256] = fp16(W)

// ---------------- PTX helpers (baseline sm_80+ only) ----------------
__device__ __forceinline__ uint32_t smem_u32(const void* p) {
    uint32_t a;
    asm("{ .reg .u64 t; cvta.to.shared.u64 t, %1; cvt.u32.u64 %0, t; }" : "=r"(a) : "l"(p));
    return a;
}
__device__ __forceinline__ void cp16(uint32_t dst, const void* src) {
    asm volatile("cp.async.cg.shared.global [%0], [%1], 16;" :: "r"(dst), "l"(src));
}
#define CP_COMMIT()  asm volatile("cp.async.commit_group;" ::: "memory")
#define CP_WAIT1()   asm volatile("cp.async.wait_group 1;" ::: "memory")
#define CP_WAIT0()   asm volatile("cp.async.wait_group 0;" ::: "memory")

__device__ __forceinline__ void ldsm4(uint32_t* r, uint32_t addr) {
    asm volatile("ldmatrix.sync.aligned.m8n8.x4.shared.b16 {%0,%1,%2,%3}, [%4];"
                 : "=r"(r[0]), "=r"(r[1]), "=r"(r[2]), "=r"(r[3]) : "r"(addr));
}
__device__ __forceinline__ void mma16816(float* d, const uint32_t* a, const uint32_t* b) {
    asm volatile(
        "mma.sync.aligned.m16n8k16.row.col.f32.f16.f16.f32 "
        "{%0,%1,%2,%3}, {%4,%5,%6,%7}, {%8,%9}, {%0,%1,%2,%3};"
        : "+f"(d[0]), "+f"(d[1]), "+f"(d[2]), "+f"(d[3])
        : "r"(a[0]), "r"(a[1]), "r"(a[2]), "r"(a[3]), "r"(b[0]), "r"(b[1]));
}

// ---------------- small helper ----------------
__device__ __forceinline__ float block_reduce_sum(float v) {
    __shared__ float s[32];
    int lane = threadIdx.x & 31;
    int w    = threadIdx.x >> 5;
    #pragma unroll
    for (int o = 16; o; o >>= 1) v += __shfl_down_sync(0xffffffffu, v, o);
    __syncthreads();
    if (lane == 0) s[w] = v;
    __syncthreads();
    int nw = blockDim.x >> 5;
    v = (threadIdx.x < nw) ? s[threadIdx.x] : 0.0f;
    if (w == 0) {
        #pragma unroll
        for (int o = 16; o; o >>= 1) v += __shfl_down_sync(0xffffffffu, v, o);
        if (lane == 0) s[0] = v;
    }
    __syncthreads();
    return s[0];
}

// ---------------- kernel 1: unpack targets (int32 vs int64 detection) ----------------
__global__ void k_unpack_targets(const int* __restrict__ traw) {
    __shared__ int oddnz;
    if (threadIdx.x == 0) oddnz = 0;
    __syncthreads();
    if (threadIdx.x < B / 2) {
        if (traw[2 * threadIdx.x + 1] != 0) atomicOr(&oddnz, 1);
    }
    __syncthreads();
    int is64 = (oddnz == 0);
    int b = threadIdx.x;
    g_targets[b] = is64 ? traw[2 * b] : traw[b];
}

// ---------------- kernel 2: normalize features + target logit + A' split ----------------
__global__ void k_normalize_tl(const float* __restrict__ features,
                               const float* __restrict__ weight) {
    int b = blockIdx.x;
    int d = threadIdx.x;
    float v = features[b * D + d];
    float ss = block_reduce_sum(v * v);
    float inv = 1.0f / fmaxf(sqrtf(ss), EPS_N);
    float f = v * inv;
    g_fnorm[b * D + d] = f;

    __half hi = __float2half(f);
    __half lo = __float2half(f - __half2float(hi));
    g_A[b * KA + d]     = hi;
    g_A[b * KA + D + d] = lo;

    int tgt = g_targets[b];
    float p = f * weight[(size_t)tgt * D + d];
    float dot = block_reduce_sum(p);
    if (d == 0) g_tl[b] = dot;
}

// ---------------- kernel 3: t_new + per-row margin params ----------------
__global__ void k_row_params(const float* __restrict__ t_in,
                             float* __restrict__ out_t) {
    int b = threadIdx.x;           // blockDim = 512
    float tl = g_tl[b];
    float m = block_reduce_sum(tl) * (1.0f / (float)B);
    if (b == 0) {
        float tn = m * 0.01f + 0.99f * t_in[0];
        g_tnew = tn;
        out_t[0] = tn;
    }
    float sn = sqrtf(fmaxf(1.0f - tl * tl, 0.0f));
    float ctm = tl * COS_M - sn * SIN_M;
    g_ctm[b] = ctm;
    g_ftl[b] = (tl > THRESH) ? ctm : (tl - MM_CONST);
}

// ---------------- kernel 4: zero scratch rows for touched classes ----------------
__global__ void k_zero_scratch(float* __restrict__ scratch) {
    int b = blockIdx.x;
    int d = threadIdx.x;
    int tgt = g_targets[b];
    scratch[(size_t)tgt * D + d] = 0.0f;
}

// ---------------- kernel 5: segment-sum accumulate ----------------
__global__ void k_accumulate(float* __restrict__ scratch) {
    int b = blockIdx.x;
    int d = threadIdx.x;
    int tgt = g_targets[b];
    atomicAdd(&scratch[(size_t)tgt * D + d], g_fnorm[b * D + d]);
    if (d == 0) atomicAdd(&g_counts[tgt], 1);
}

// ---------------- kernel 6: weight update + fp16(W) conversion (warp/class) ---------
__global__ void __launch_bounds__(256)
k_weight_update(const float* __restrict__ weight,
                const float* __restrict__ scratch,
                float* __restrict__ newW) {
    int w    = threadIdx.x >> 5;
    int lane = threadIdx.x & 31;
    int c    = blockIdx.x * 8 + w;
    size_t kb = (size_t)c * KB;

    if (c >= C) {
        *(uint4*)&g_Bw[kb + lane * 8] = make_uint4(0, 0, 0, 0);
        return;
    }

    size_t idx = (size_t)c * D + lane * 8;
    float4 w0 = *(const float4*)&weight[idx];
    float4 w1 = *(const float4*)&weight[idx + 4];
    float wv[8] = {w0.x, w0.y, w0.z, w0.w, w1.x, w1.y, w1.z, w1.w};

    uint32_t hp[4];
    #pragma unroll
    for (int i = 0; i < 4; ++i) {
        __half2 h = __floats2half2_rn(wv[2 * i], wv[2 * i + 1]);
        hp[i] = *(uint32_t*)&h;
    }
    *(uint4*)&g_Bw[kb + lane * 8] = make_uint4(hp[0], hp[1], hp[2], hp[3]);

    int cnt = g_counts[c];
    if (cnt > 0) {
        float4 s0 = *(const float4*)&scratch[idx];
        float4 s1 = *(const float4*)&scratch[idx + 4];
        float sv[8] = {s0.x, s0.y, s0.z, s0.w, s1.x, s1.y, s1.z, s1.w};
        float inv_cnt = 1.0f / (float)cnt;
        float u[8], ss = 0.0f;
        #pragma unroll
        for (int i = 0; i < 8; ++i) {
            u[i] = 0.5f * wv[i] + 0.5f * (sv[i] * inv_cnt);
            ss += u[i] * u[i];
        }
        #pragma unroll
        for (int o = 16; o; o >>= 1) ss += __shfl_xor_sync(0xffffffffu, ss, o);
        float inv = 1.0f / fmaxf(sqrtf(ss), EPS_N);
        *(float4*)&newW[idx]     = make_float4(u[0] * inv, u[1] * inv, u[2] * inv, u[3] * inv);
        *(float4*)&newW[idx + 4] = make_float4(u[4] * inv, u[5] * inv, u[6] * inv, u[7] * inv);
    } else {
        *(float4*)&newW[idx]     = w0;
        *(float4*)&newW[idx + 4] = w1;
    }
}

// ---------------- kernel 7: restore counts invariant (touched classes only) --------
__global__ void k_cleanup() {
    g_counts[g_targets[threadIdx.x]] = 0;
}

// ---------------- kernel 8: mma.sync GEMM + ArcFace epilogue ----------------
// CTA: 128(m) x 256(n). 8 warps in 2(m) x 4(n); warp tile 64x64.
// 4 K-chunks over D=256; each chunk loads B once + A-hi + A-lo (both MMA'd
// into the same accumulator) -> B read exactly once, fp32-equivalent result.
#define BKE      64                     // K elements per chunk
#define NCHUNK   4
#define STRIDE   144                    // padded row bytes (64*2 + 16)
#define TILE_A   (128 * STRIDE)         // 18432
#define TILE_BB  (256 * STRIDE)         // 36864
#define STAGE_B  (2 * TILE_A + TILE_BB) // 73728 (A-hi + A-lo + B)
#define SMEM_G   (2 * STAGE_B)          // 147456

__device__ __forceinline__ void load_tiles(int chunk, int stage, uint32_t sb,
                                           int m0, int n0) {
    uint32_t base = sb + stage * STAGE_B;
    const char* Asrc = (const char*)g_A;
    const char* Bsrc = (const char*)g_Bw;
    // A: hi part (cols chunk*64) and lo part (cols 256 + chunk*64), 128 rows each
    #pragma unroll
    for (int i = 0; i < 8; ++i) {
        int idx  = threadIdx.x + i * 256;       // 0..2047
        int part = idx >> 10;                   // 0 = hi, 1 = lo
        int row  = (idx >> 3) & 127;
        int seg  = idx & 7;
        uint32_t so = part * TILE_A + row * STRIDE + seg * 16;
        cp16(base + so,
             Asrc + ((size_t)(m0 + row) * KA + part * D + chunk * BKE) * 2 + seg * 16);
    }
    // B: 256 rows
    #pragma unroll
    for (int i = 0; i < 8; ++i) {
        int idx = threadIdx.x + i * 256;        // 0..2047
        int row = idx >> 3;
        int seg = idx & 7;
        uint32_t so = 2 * TILE_A + row * STRIDE + seg * 16;
        cp16(base + so,
             Bsrc + ((size_t)(n0 + row) * KB + chunk * BKE) * 2 + seg * 16);
    }
    CP_COMMIT();
}

__global__ void __launch_bounds__(256, 1)
k_gemm_mma(float* __restrict__ pred) {
    extern __shared__ char smem[];
    uint32_t sb = smem_u32(smem);
    const int tid  = threadIdx.x;
    const int wid  = tid >> 5;
    const int lane = tid & 31;
    const int wm   = wid >> 2;          // 0..1
    const int wn   = wid & 3;           // 0..3
    const int g    = lane >> 2;         // 0..7
    const int tig  = lane & 3;          // 0..3
    const int m0   = blockIdx.x * 128;  // m fastest -> B-tile L2 reuse
    const int n0   = blockIdx.y * 256;

    // per-lane ldmatrix base offsets (within a 128/256-row tile)
    const uint32_t a_off = (uint32_t)(wm * 64 + (lane & 7) + ((lane >> 3) & 1) * 8) * STRIDE
                         + ((lane >> 4) & 1) * 16;
    const uint32_t b_off = (uint32_t)(wn * 64 + (lane & 7) + ((lane >> 4) & 1) * 8) * STRIDE
                         + ((lane >> 3) & 1) * 16;

    float acc[4][8][4];
    #pragma unroll
    for (int i = 0; i < 4; ++i)
        #pragma unroll
        for (int j = 0; j < 8; ++j)
            #pragma unroll
            for (int r = 0; r < 4; ++r) acc[i][j][r] = 0.0f;

    load_tiles(0, 0, sb, m0, n0);
    load_tiles(1, 1, sb, m0, n0);

    for (int j = 0; j < NCHUNK; ++j) {
        if (j + 1 < NCHUNK) { CP_WAIT1(); } else { CP_WAIT0(); }
        __syncthreads();
        const int stage = j & 1;
        const uint32_t at = sb + stage * STAGE_B + a_off;           // A-hi
        const uint32_t bt = sb + stage * STAGE_B + 2 * TILE_A + b_off;

        #pragma unroll
        for (int kk = 0; kk < 4; ++kk) {
            uint32_t b[8][2];
            #pragma unroll
            for (int p = 0; p < 4; ++p) {
                uint32_t r[4];
                ldsm4(r, bt + p * 16 * STRIDE + kk * 32);
                b[2 * p][0]     = r[0];
                b[2 * p][1]     = r[1];
                b[2 * p + 1][0] = r[2];
                b[2 * p + 1][1] = r[3];
            }
            uint32_t a[4][4];
            #pragma unroll
            for (int mi = 0; mi < 4; ++mi)
                ldsm4(a[mi], at + mi * 16 * STRIDE + kk * 32);      // A-hi
            #pragma unroll
            for (int mi = 0; mi < 4; ++mi)
                #pragma unroll
                for (int nj = 0; nj < 8; ++nj)
                    mma16816(acc[mi][nj], a[mi], b[nj]);
            #pragma unroll
            for (int mi = 0; mi < 4; ++mi)
                ldsm4(a[mi], at + TILE_A + mi * 16 * STRIDE + kk * 32);  // A-lo
            #pragma unroll
            for (int mi = 0; mi < 4; ++mi)
                #pragma unroll
                for (int nj = 0; nj < 8; ++nj)
                    mma16816(acc[mi][nj], a[mi], b[nj]);
        }
        __syncthreads();                        // stage free before refill
        if (j + 2 < NCHUNK) load_tiles(j + 2, stage, sb, m0, n0);
    }

    // ---- fused ArcFace epilogue ----
    const float tn = g_tnew;
    #pragma unroll
    for (int mi = 0; mi < 4; ++mi) {
        int r0 = m0 + wm * 64 + mi * 16 + g;
        #pragma unroll
        for (int half = 0; half < 2; ++half) {
            int brow = r0 + half * 8;
            int tgt   = g_targets[brow];
            float ctm = g_ctm[brow];
            float ftl = g_ftl[brow];
            size_t rowbase = (size_t)brow * C;
            #pragma unroll
            for (int nj = 0; nj < 8; ++nj) {
                int c = n0 + wn * 64 + nj * 8 + tig * 2;
                float v0 = acc[mi][nj][half * 2 + 0];
                float v1 = acc[mi][nj][half * 2 + 1];
                v0 = (v0 > ctm) ? v0 * (tn + v0) : v0;
                v1 = (v1 > ctm) ? v1 * (tn + v1) : v1;
                if (c == tgt)     v0 = ftl;
                if (c + 1 == tgt) v1 = ftl;
                v0 *= S_SCALE;
                v1 *= S_SCALE;
                if (c + 1 < C) {
                    *(float2*)&pred[rowbase + c] = make_float2(v0, v1);
                } else if (c < C) {
                    pred[rowbase + c] = v0;
                }
            }
        }
    }
}

// ---------------- launch ----------------
extern "C" void kernel_launch(void* const* d_in, const int* in_sizes, int n_in,
                              void* d_out, int out_size) {
    const float* features = (const float*)d_in[0];
    const int*   traw     = (const int*)d_in[1];
    const float* weight   = (const float*)d_in[2];
    const float* t_in     = (const float*)d_in[3];

    float* out    = (float*)d_out;
    float* pred   = out;                        // [B, C]
    float* newW   = out + PRED_ELEMS;           // [C, D]
    float* out_t  = out + PRED_ELEMS + W_ELEMS; // [1]
    float* scratch = pred;                      // reuse pred region as segment-sum scratch

    cudaFuncSetAttribute(k_gemm_mma, cudaFuncAttributeMaxDynamicSharedMemorySize, SMEM_G);

    k_unpack_targets<<<1, B>>>(traw);
    k_normalize_tl<<<B, D>>>(features, weight);
    k_row_params<<<1, B>>>(t_in, out_t);
    k_zero_scratch<<<B, D>>>(scratch);
    k_accumulate<<<B, D>>>(scratch);
    k_weight_update<<<CPAD / 8, 256>>>(weight, scratch, newW);
    k_cleanup<<<1, B>>>();

    dim3 grid(B / 128, CPAD / 256);             // (4, 391), m fastest
    k_gemm_mma<<<grid, 256, SMEM_G>>>(pred);
}

// round 7
// speedup vs baseline: 1.0172x; 1.0172x over previous
#include <cuda_runtime.h>
#include <cuda_fp16.h>
#include <math.h>
#include <stdint.h>

// ---------------- problem constants ----------------
#define B   512
#define D   256
#define C   100000
#define CPAD 100096              // padded to multiple of 256

#define S_SCALE   30.0f
#define COS_M     0.8775825618903728f
#define SIN_M     0.479425538604203f
#define THRESH   (-0.8775825618903728f)
#define MM_CONST  0.2397127693021015f
#define EPS_N     1e-12f

#define PRED_ELEMS   ((size_t)B * C)
#define W_ELEMS      ((size_t)C * D)

// ---------------- device scratch ----------------
__device__ float g_fnorm[B * D];
__device__ float g_tl[B];
__device__ float g_ctm[B];
__device__ float g_ftl[B];
__device__ float g_tnew;
__device__ int   g_counts[C];    // invariant: all-zero at kernel_launch entry
__device__ int   g_targets[B];

// A fragment-packed: [mblk(32)][kch(8: part*4+chunk)][kk(4)][lane16(32)] x uint4
// uint4 index = ((mblk*8 + kch)*4 + kk)*32 + lane16
__device__ uint4 g_Afrag[32 * 8 * 4 * 32];
// B fragment-packed: [nblk(CPAD/8)][chunk(4)][q(2)][lane16(32)] x uint4
// uint4 index = ((nblk*4 + chunk)*2 + q)*32 + lane16
__device__ uint4 g_Bfrag[(size_t)(CPAD / 8) * 4 * 2 * 32];

// ---------------- PTX helpers ----------------
__device__ __forceinline__ void mma16816(float* d, const uint32_t* a, const uint32_t* b) {
    asm volatile(
        "mma.sync.aligned.m16n8k16.row.col.f32.f16.f16.f32 "
        "{%0,%1,%2,%3}, {%4,%5,%6,%7}, {%8,%9}, {%0,%1,%2,%3};"
        : "+f"(d[0]), "+f"(d[1]), "+f"(d[2]), "+f"(d[3])
        : "r"(a[0]), "r"(a[1]), "r"(a[2]), "r"(a[3]), "r"(b[0]), "r"(b[1]));
}

// ---------------- small helper ----------------
__device__ __forceinline__ float block_reduce_sum(float v) {
    __shared__ float s[32];
    int lane = threadIdx.x & 31;
    int w    = threadIdx.x >> 5;
    #pragma unroll
    for (int o = 16; o; o >>= 1) v += __shfl_down_sync(0xffffffffu, v, o);
    __syncthreads();
    if (lane == 0) s[w] = v;
    __syncthreads();
    int nw = blockDim.x >> 5;
    v = (threadIdx.x < nw) ? s[threadIdx.x] : 0.0f;
    if (w == 0) {
        #pragma unroll
        for (int o = 16; o; o >>= 1) v += __shfl_down_sync(0xffffffffu, v, o);
        if (lane == 0) s[0] = v;
    }
    __syncthreads();
    return s[0];
}

// ---------------- kernel 1: unpack targets (int32 vs int64 detection) ----------------
__global__ void k_unpack_targets(const int* __restrict__ traw) {
    __shared__ int oddnz;
    if (threadIdx.x == 0) oddnz = 0;
    __syncthreads();
    if (threadIdx.x < B / 2) {
        if (traw[2 * threadIdx.x + 1] != 0) atomicOr(&oddnz, 1);
    }
    __syncthreads();
    int is64 = (oddnz == 0);
    int b = threadIdx.x;
    g_targets[b] = is64 ? traw[2 * b] : traw[b];
}

// ---------------- kernel 2: normalize features + target logit ----------------
__global__ void k_normalize_tl(const float* __restrict__ features,
                               const float* __restrict__ weight) {
    int b = blockIdx.x;
    int d = threadIdx.x;
    float v = features[b * D + d];
    float ss = block_reduce_sum(v * v);
    float inv = 1.0f / fmaxf(sqrtf(ss), EPS_N);
    float f = v * inv;
    g_fnorm[b * D + d] = f;

    int tgt = g_targets[b];
    float p = f * weight[(size_t)tgt * D + d];
    float dot = block_reduce_sum(p);
    if (d == 0) g_tl[b] = dot;
}

// ---------------- kernel 3: pack A fragments ([fhi|flo] fp16 split) ----------------
// One thread per 16B packet. 32768 packets.
__global__ void __launch_bounds__(256)
k_pack_A() {
    int tid = blockIdx.x * 256 + threadIdx.x;     // 0..32767
    int lane16 = tid & 31;
    int g    = lane16 >> 2;
    int tig  = lane16 & 3;
    int kk   = (tid >> 5) & 3;
    int kch  = (tid >> 7) & 7;
    int mblk = tid >> 10;
    int part  = kch >> 2;
    int chunk = kch & 3;
    int k0 = chunk * 64 + kk * 16;
    int m  = mblk * 16 + g;
    int c0 = k0 + tig * 2;
    int c1 = c0 + 8;

    float f[8];
    f[0] = g_fnorm[m * D + c0];       f[1] = g_fnorm[m * D + c0 + 1];
    f[2] = g_fnorm[(m + 8) * D + c0]; f[3] = g_fnorm[(m + 8) * D + c0 + 1];
    f[4] = g_fnorm[m * D + c1];       f[5] = g_fnorm[m * D + c1 + 1];
    f[6] = g_fnorm[(m + 8) * D + c1]; f[7] = g_fnorm[(m + 8) * D + c1 + 1];

    __half h[8];
    #pragma unroll
    for (int i = 0; i < 8; ++i) {
        __half hi = __float2half(f[i]);
        h[i] = part ? __float2half(f[i] - __half2float(hi)) : hi;
    }
    uint4 out;
    __half2 p0(h[0], h[1]); out.x = *(uint32_t*)&p0;
    __half2 p1(h[2], h[3]); out.y = *(uint32_t*)&p1;
    __half2 p2(h[4], h[5]); out.z = *(uint32_t*)&p2;
    __half2 p3(h[6], h[7]); out.w = *(uint32_t*)&p3;
    g_Afrag[tid] = out;
}

// ---------------- kernel 4: t_new + per-row margin params ----------------
__global__ void k_row_params(const float* __restrict__ t_in,
                             float* __restrict__ out_t) {
    int b = threadIdx.x;           // blockDim = 512
    float tl = g_tl[b];
    float m = block_reduce_sum(tl) * (1.0f / (float)B);
    if (b == 0) {
        float tn = m * 0.01f + 0.99f * t_in[0];
        g_tnew = tn;
        out_t[0] = tn;
    }
    float sn = sqrtf(fmaxf(1.0f - tl * tl, 0.0f));
    float ctm = tl * COS_M - sn * SIN_M;
    g_ctm[b] = ctm;
    g_ftl[b] = (tl > THRESH) ? ctm : (tl - MM_CONST);
}

// ---------------- kernel 5: zero scratch rows for touched classes ----------------
__global__ void k_zero_scratch(float* __restrict__ scratch) {
    int b = blockIdx.x;
    int d = threadIdx.x;
    int tgt = g_targets[b];
    scratch[(size_t)tgt * D + d] = 0.0f;
}

// ---------------- kernel 6: segment-sum accumulate ----------------
__global__ void k_accumulate(float* __restrict__ scratch) {
    int b = blockIdx.x;
    int d = threadIdx.x;
    int tgt = g_targets[b];
    atomicAdd(&scratch[(size_t)tgt * D + d], g_fnorm[b * D + d]);
    if (d == 0) atomicAdd(&g_counts[tgt], 1);
}

// ---------------- kernel 7: weight update + fp16(W) B-fragment pack (warp/class) ----
__global__ void __launch_bounds__(256)
k_weight_update(const float* __restrict__ weight,
                const float* __restrict__ scratch,
                float* __restrict__ newW) {
    int w    = threadIdx.x >> 5;
    int lane = threadIdx.x & 31;
    int c    = blockIdx.x * 8 + w;
    int nblk = c >> 3;
    int g    = c & 7;

    float wv[8];
    if (c < C) {
        size_t idx = (size_t)c * D + lane * 8;
        float4 w0 = *(const float4*)&weight[idx];
        float4 w1 = *(const float4*)&weight[idx + 4];
        wv[0] = w0.x; wv[1] = w0.y; wv[2] = w0.z; wv[3] = w0.w;
        wv[4] = w1.x; wv[5] = w1.y; wv[6] = w1.z; wv[7] = w1.w;
    } else {
        #pragma unroll
        for (int i = 0; i < 8; ++i) wv[i] = 0.0f;
    }

    // fragment-packed fp16 store of OLD weight
    uint32_t* Bf32 = (uint32_t*)g_Bfrag;
    #pragma unroll
    for (int jj = 0; jj < 4; ++jj) {
        int k     = lane * 8 + jj * 2;
        int chunk = k >> 6;
        int ck    = k & 63;
        int kk    = ck >> 4;
        int q     = kk >> 1;
        int ii    = kk & 1;
        int h     = (ck >> 3) & 1;
        int tg    = (ck & 7) >> 1;
        size_t off32 = (((size_t)nblk * 4 + chunk) * 2 + q) * 128
                     + g * 16 + tg * 4 + ii * 2 + h;
        __half2 hp = __floats2half2_rn(wv[2 * jj], wv[2 * jj + 1]);
        Bf32[off32] = *(uint32_t*)&hp;
    }

    if (c >= C) return;

    size_t idx = (size_t)c * D + lane * 8;
    int cnt = g_counts[c];
    if (cnt > 0) {
        float4 s0 = *(const float4*)&scratch[idx];
        float4 s1 = *(const float4*)&scratch[idx + 4];
        float sv[8] = {s0.x, s0.y, s0.z, s0.w, s1.x, s1.y, s1.z, s1.w};
        float inv_cnt = 1.0f / (float)cnt;
        float u[8], ss = 0.0f;
        #pragma unroll
        for (int i = 0; i < 8; ++i) {
            u[i] = 0.5f * wv[i] + 0.5f * (sv[i] * inv_cnt);
            ss += u[i] * u[i];
        }
        #pragma unroll
        for (int o = 16; o; o >>= 1) ss += __shfl_xor_sync(0xffffffffu, ss, o);
        float inv = 1.0f / fmaxf(sqrtf(ss), EPS_N);
        *(float4*)&newW[idx]     = make_float4(u[0] * inv, u[1] * inv, u[2] * inv, u[3] * inv);
        *(float4*)&newW[idx + 4] = make_float4(u[4] * inv, u[5] * inv, u[6] * inv, u[7] * inv);
    } else {
        *(float4*)&newW[idx]     = make_float4(wv[0], wv[1], wv[2], wv[3]);
        *(float4*)&newW[idx + 4] = make_float4(wv[4], wv[5], wv[6], wv[7]);
    }
}

// ---------------- kernel 8: restore counts invariant ----------------
__global__ void k_cleanup() {
    g_counts[g_targets[threadIdx.x]] = 0;
}

// ---------------- kernel 9: smem-free mma.sync GEMM + ArcFace epilogue ----------------
// CTA 128(m) x 256(n), 8 warps 2(m) x 4(n), warp tile 64x64.
// All operands loaded directly from fragment-packed global via coalesced LDG.128.
__global__ void __launch_bounds__(256, 1)
k_gemm_mma(float* __restrict__ pred) {
    const int tid  = threadIdx.x;
    const int wid  = tid >> 5;
    const int lane = tid & 31;
    const int wm   = wid >> 2;          // 0..1
    const int wn   = wid & 3;           // 0..3
    const int g    = lane >> 2;         // 0..7
    const int tig  = lane & 3;          // 0..3
    const int m0   = blockIdx.x * 128;  // m fastest -> B L2 reuse
    const int n0   = blockIdx.y * 256;

    const int mblk0 = (m0 >> 4) + wm * 4;       // 4 m-blocks of 16 rows
    const int nblk0 = (n0 >> 3) + wn * 8;       // 8 n-blocks of 8 rows

    float acc[4][8][4];
    #pragma unroll
    for (int i = 0; i < 4; ++i)
        #pragma unroll
        for (int j = 0; j < 8; ++j)
            #pragma unroll
            for (int r = 0; r < 4; ++r) acc[i][j][r] = 0.0f;

    for (int j = 0; j < 4; ++j) {               // K chunks of 64
        #pragma unroll
        for (int q = 0; q < 2; ++q) {           // kk pairs
            uint4 bv[8];
            #pragma unroll
            for (int nj = 0; nj < 8; ++nj)
                bv[nj] = g_Bfrag[(((size_t)(nblk0 + nj) * 4 + j) * 2 + q) * 32 + lane];
            #pragma unroll
            for (int i = 0; i < 2; ++i) {       // kk = 2q + i
                const int kk = 2 * q + i;
                #pragma unroll
                for (int p = 0; p < 2; ++p) {   // fhi / flo part
                    uint4 av[4];
                    #pragma unroll
                    for (int mi = 0; mi < 4; ++mi)
                        av[mi] = g_Afrag[(((mblk0 + mi) * 8 + p * 4 + j) * 4 + kk) * 32 + lane];
                    #pragma unroll
                    for (int mi = 0; mi < 4; ++mi) {
                        #pragma unroll
                        for (int nj = 0; nj < 8; ++nj) {
                            uint32_t bb[2];
                            bb[0] = i ? bv[nj].z : bv[nj].x;
                            bb[1] = i ? bv[nj].w : bv[nj].y;
                            mma16816(acc[mi][nj], (const uint32_t*)&av[mi], bb);
                        }
                    }
                }
            }
        }
    }

    // ---- fused ArcFace epilogue ----
    const float tn = g_tnew;
    #pragma unroll
    for (int mi = 0; mi < 4; ++mi) {
        int r0 = m0 + wm * 64 + mi * 16 + g;
        #pragma unroll
        for (int half = 0; half < 2; ++half) {
            int brow = r0 + half * 8;
            int tgt   = g_targets[brow];
            float ctm = g_ctm[brow];
            float ftl = g_ftl[brow];
            size_t rowbase = (size_t)brow * C;
            #pragma unroll
            for (int nj = 0; nj < 8; ++nj) {
                int c = n0 + wn * 64 + nj * 8 + tig * 2;
                float v0 = acc[mi][nj][half * 2 + 0];
                float v1 = acc[mi][nj][half * 2 + 1];
                v0 = (v0 > ctm) ? v0 * (tn + v0) : v0;
                v1 = (v1 > ctm) ? v1 * (tn + v1) : v1;
                if (c == tgt)     v0 = ftl;
                if (c + 1 == tgt) v1 = ftl;
                v0 *= S_SCALE;
                v1 *= S_SCALE;
                if (c + 1 < C) {
                    *(float2*)&pred[rowbase + c] = make_float2(v0, v1);
                } else if (c < C) {
                    pred[rowbase + c] = v0;
                }
            }
        }
    }
}

// ---------------- launch ----------------
extern "C" void kernel_launch(void* const* d_in, const int* in_sizes, int n_in,
                              void* d_out, int out_size) {
    const float* features = (const float*)d_in[0];
    const int*   traw     = (const int*)d_in[1];
    const float* weight   = (const float*)d_in[2];
    const float* t_in     = (const float*)d_in[3];

    float* out    = (float*)d_out;
    float* pred   = out;                        // [B, C]
    float* newW   = out + PRED_ELEMS;           // [C, D]
    float* out_t  = out + PRED_ELEMS + W_ELEMS; // [1]
    float* scratch = pred;                      // reuse pred region as segment-sum scratch

    k_unpack_targets<<<1, B>>>(traw);
    k_normalize_tl<<<B, D>>>(features, weight);
    k_pack_A<<<128, 256>>>();
    k_row_params<<<1, B>>>(t_in, out_t);
    k_zero_scratch<<<B, D>>>(scratch);
    k_accumulate<<<B, D>>>(scratch);
    k_weight_update<<<CPAD / 8, 256>>>(weight, scratch, newW);
    k_cleanup<<<1, B>>>();

    dim3 grid(B / 128, CPAD / 256);             // (4, 391), m fastest
    k_gemm_mma<<<grid, 256>>>(pred);
}

// round 8
// speedup vs baseline: 1.2655x; 1.2441x over previous
#include <cuda_runtime.h>
#include <cuda_fp16.h>
#include <math.h>
#include <stdint.h>

// ---------------- problem constants ----------------
#define B   512
#define D   256
#define C   100000
#define CPAD 100096              // padded to multiple of 256

#define S_SCALE   30.0f
#define COS_M     0.8775825618903728f
#define SIN_M     0.479425538604203f
#define THRESH   (-0.8775825618903728f)
#define MM_CONST  0.2397127693021015f
#define EPS_N     1e-12f

#define PRED_ELEMS   ((size_t)B * C)
#define W_ELEMS      ((size_t)C * D)

// ---------------- device scratch ----------------
__device__ float g_fnorm[B * D];
__device__ float g_tl[B];
__device__ float g_ctm[B];
__device__ float g_ftl[B];
__device__ float g_tnew;
__device__ int   g_counts[C];    // invariant: all-zero at kernel_launch entry
__device__ int   g_targets[B];

// A fragment-packed: [mblk(32)][chunk(4)][kk(4)][lane(32)] x uint4 (fp16 f)
__device__ uint4 g_Afrag[32 * 4 * 4 * 32];
// B fragment-packed: [nblk(CPAD/8)][chunk(4)][q(2)][lane(32)] x uint4 (fp16 W)
__device__ uint4 g_Bfrag[(size_t)(CPAD / 8) * 4 * 2 * 32];

// ---------------- PTX helpers ----------------
__device__ __forceinline__ void mma16816(float* d, const uint32_t* a, const uint32_t* b) {
    asm volatile(
        "mma.sync.aligned.m16n8k16.row.col.f32.f16.f16.f32 "
        "{%0,%1,%2,%3}, {%4,%5,%6,%7}, {%8,%9}, {%0,%1,%2,%3};"
        : "+f"(d[0]), "+f"(d[1]), "+f"(d[2]), "+f"(d[3])
        : "r"(a[0]), "r"(a[1]), "r"(a[2]), "r"(a[3]), "r"(b[0]), "r"(b[1]));
}

// ---------------- small helper ----------------
__device__ __forceinline__ float block_reduce_sum(float v) {
    __shared__ float s[32];
    int lane = threadIdx.x & 31;
    int w    = threadIdx.x >> 5;
    #pragma unroll
    for (int o = 16; o; o >>= 1) v += __shfl_down_sync(0xffffffffu, v, o);
    __syncthreads();
    if (lane == 0) s[w] = v;
    __syncthreads();
    int nw = blockDim.x >> 5;
    v = (threadIdx.x < nw) ? s[threadIdx.x] : 0.0f;
    if (w == 0) {
        #pragma unroll
        for (int o = 16; o; o >>= 1) v += __shfl_down_sync(0xffffffffu, v, o);
        if (lane == 0) s[0] = v;
    }
    __syncthreads();
    return s[0];
}

// ---------------- kernel 1: unpack targets (int32 vs int64 detection) ----------------
__global__ void k_unpack_targets(const int* __restrict__ traw) {
    __shared__ int oddnz;
    if (threadIdx.x == 0) oddnz = 0;
    __syncthreads();
    if (threadIdx.x < B / 2) {
        if (traw[2 * threadIdx.x + 1] != 0) atomicOr(&oddnz, 1);
    }
    __syncthreads();
    int is64 = (oddnz == 0);
    int b = threadIdx.x;
    g_targets[b] = is64 ? traw[2 * b] : traw[b];
}

// ---------------- kernel 2: normalize features + target logit ----------------
__global__ void k_normalize_tl(const float* __restrict__ features,
                               const float* __restrict__ weight) {
    int b = blockIdx.x;
    int d = threadIdx.x;
    float v = features[b * D + d];
    float ss = block_reduce_sum(v * v);
    float inv = 1.0f / fmaxf(sqrtf(ss), EPS_N);
    float f = v * inv;
    g_fnorm[b * D + d] = f;

    int tgt = g_targets[b];
    float p = f * weight[(size_t)tgt * D + d];
    float dot = block_reduce_sum(p);
    if (d == 0) g_tl[b] = dot;
}

// ---------------- kernel 3: pack A fragments (fp16 f) ----------------
// One thread per 16B packet. 16384 packets.
__global__ void __launch_bounds__(256)
k_pack_A() {
    int tid = blockIdx.x * 256 + threadIdx.x;     // 0..16383
    int lane16 = tid & 31;
    int g    = lane16 >> 2;
    int tig  = lane16 & 3;
    int kk   = (tid >> 5) & 3;
    int chunk = (tid >> 7) & 3;
    int mblk = tid >> 9;
    int k0 = chunk * 64 + kk * 16;
    int m  = mblk * 16 + g;
    int c0 = k0 + tig * 2;
    int c1 = c0 + 8;

    float f[8];
    f[0] = g_fnorm[m * D + c0];       f[1] = g_fnorm[m * D + c0 + 1];
    f[2] = g_fnorm[(m + 8) * D + c0]; f[3] = g_fnorm[(m + 8) * D + c0 + 1];
    f[4] = g_fnorm[m * D + c1];       f[5] = g_fnorm[m * D + c1 + 1];
    f[6] = g_fnorm[(m + 8) * D + c1]; f[7] = g_fnorm[(m + 8) * D + c1 + 1];

    uint4 out;
    __half2 p0 = __floats2half2_rn(f[0], f[1]); out.x = *(uint32_t*)&p0;
    __half2 p1 = __floats2half2_rn(f[2], f[3]); out.y = *(uint32_t*)&p1;
    __half2 p2 = __floats2half2_rn(f[4], f[5]); out.z = *(uint32_t*)&p2;
    __half2 p3 = __floats2half2_rn(f[6], f[7]); out.w = *(uint32_t*)&p3;
    g_Afrag[tid] = out;
}

// ---------------- kernel 4: t_new + per-row margin params ----------------
__global__ void k_row_params(const float* __restrict__ t_in,
                             float* __restrict__ out_t) {
    int b = threadIdx.x;           // blockDim = 512
    float tl = g_tl[b];
    float m = block_reduce_sum(tl) * (1.0f / (float)B);
    if (b == 0) {
        float tn = m * 0.01f + 0.99f * t_in[0];
        g_tnew = tn;
        out_t[0] = tn;
    }
    float sn = sqrtf(fmaxf(1.0f - tl * tl, 0.0f));
    float ctm = tl * COS_M - sn * SIN_M;
    g_ctm[b] = ctm;
    g_ftl[b] = (tl > THRESH) ? ctm : (tl - MM_CONST);
}

// ---------------- kernel 5: zero scratch rows for touched classes ----------------
__global__ void k_zero_scratch(float* __restrict__ scratch) {
    int b = blockIdx.x;
    int d = threadIdx.x;
    int tgt = g_targets[b];
    scratch[(size_t)tgt * D + d] = 0.0f;
}

// ---------------- kernel 6: segment-sum accumulate ----------------
__global__ void k_accumulate(float* __restrict__ scratch) {
    int b = blockIdx.x;
    int d = threadIdx.x;
    int tgt = g_targets[b];
    atomicAdd(&scratch[(size_t)tgt * D + d], g_fnorm[b * D + d]);
    if (d == 0) atomicAdd(&g_counts[tgt], 1);
}

// ---------------- kernel 7: weight update + fp16(W) B-fragment pack (warp/class) ----
__global__ void __launch_bounds__(256)
k_weight_update(const float* __restrict__ weight,
                const float* __restrict__ scratch,
                float* __restrict__ newW) {
    int w    = threadIdx.x >> 5;
    int lane = threadIdx.x & 31;
    int c    = blockIdx.x * 8 + w;
    int nblk = c >> 3;
    int g    = c & 7;

    float wv[8];
    if (c < C) {
        size_t idx = (size_t)c * D + lane * 8;
        float4 w0 = *(const float4*)&weight[idx];
        float4 w1 = *(const float4*)&weight[idx + 4];
        wv[0] = w0.x; wv[1] = w0.y; wv[2] = w0.z; wv[3] = w0.w;
        wv[4] = w1.x; wv[5] = w1.y; wv[6] = w1.z; wv[7] = w1.w;
    } else {
        #pragma unroll
        for (int i = 0; i < 8; ++i) wv[i] = 0.0f;
    }

    // fragment-packed fp16 store of OLD weight
    uint32_t* Bf32 = (uint32_t*)g_Bfrag;
    #pragma unroll
    for (int jj = 0; jj < 4; ++jj) {
        int k     = lane * 8 + jj * 2;
        int chunk = k >> 6;
        int ck    = k & 63;
        int kk    = ck >> 4;
        int q     = kk >> 1;
        int ii    = kk & 1;
        int h     = (ck >> 3) & 1;
        int tg    = (ck & 7) >> 1;
        size_t off32 = (((size_t)nblk * 4 + chunk) * 2 + q) * 128
                     + g * 16 + tg * 4 + ii * 2 + h;
        __half2 hp = __floats2half2_rn(wv[2 * jj], wv[2 * jj + 1]);
        Bf32[off32] = *(uint32_t*)&hp;
    }

    if (c >= C) return;

    size_t idx = (size_t)c * D + lane * 8;
    int cnt = g_counts[c];
    if (cnt > 0) {
        float4 s0 = *(const float4*)&scratch[idx];
        float4 s1 = *(const float4*)&scratch[idx + 4];
        float sv[8] = {s0.x, s0.y, s0.z, s0.w, s1.x, s1.y, s1.z, s1.w};
        float inv_cnt = 1.0f / (float)cnt;
        float u[8], ss = 0.0f;
        #pragma unroll
        for (int i = 0; i < 8; ++i) {
            u[i] = 0.5f * wv[i] + 0.5f * (sv[i] * inv_cnt);
            ss += u[i] * u[i];
        }
        #pragma unroll
        for (int o = 16; o; o >>= 1) ss += __shfl_xor_sync(0xffffffffu, ss, o);
        float inv = 1.0f / fmaxf(sqrtf(ss), EPS_N);
        *(float4*)&newW[idx]     = make_float4(u[0] * inv, u[1] * inv, u[2] * inv, u[3] * inv);
        *(float4*)&newW[idx + 4] = make_float4(u[4] * inv, u[5] * inv, u[6] * inv, u[7] * inv);
    } else {
        *(float4*)&newW[idx]     = make_float4(wv[0], wv[1], wv[2], wv[3]);
        *(float4*)&newW[idx + 4] = make_float4(wv[4], wv[5], wv[6], wv[7]);
    }
}

// ---------------- kernel 8: restore counts invariant ----------------
__global__ void k_cleanup() {
    g_counts[g_targets[threadIdx.x]] = 0;
}

// ---------------- kernel 9: smem-free mma.sync GEMM + ArcFace epilogue ----------------
// CTA 128(m) x 256(n), 8 warps 2(m) x 4(n), warp tile 64x64, K = 256.
// Operands loaded directly from fragment-packed global via coalesced LDG.128.
__global__ void __launch_bounds__(256, 1)
k_gemm_mma(float* __restrict__ pred) {
    const int tid  = threadIdx.x;
    const int wid  = tid >> 5;
    const int lane = tid & 31;
    const int wm   = wid >> 2;          // 0..1
    const int wn   = wid & 3;           // 0..3
    const int g    = lane >> 2;         // 0..7
    const int tig  = lane & 3;          // 0..3
    const int m0   = blockIdx.x * 128;  // m fastest -> B L2 reuse
    const int n0   = blockIdx.y * 256;

    const int mblk0 = (m0 >> 4) + wm * 4;       // 4 m-blocks of 16 rows
    const int nblk0 = (n0 >> 3) + wn * 8;       // 8 n-blocks of 8 rows

    float acc[4][8][4];
    #pragma unroll
    for (int i = 0; i < 4; ++i)
        #pragma unroll
        for (int j = 0; j < 8; ++j)
            #pragma unroll
            for (int r = 0; r < 4; ++r) acc[i][j][r] = 0.0f;

    for (int j = 0; j < 4; ++j) {               // K chunks of 64
        #pragma unroll
        for (int q = 0; q < 2; ++q) {           // kk pairs
            uint4 bv[8];
            #pragma unroll
            for (int nj = 0; nj < 8; ++nj)
                bv[nj] = g_Bfrag[(((size_t)(nblk0 + nj) * 4 + j) * 2 + q) * 32 + lane];
            #pragma unroll
            for (int i = 0; i < 2; ++i) {       // kk = 2q + i
                const int kk = 2 * q + i;
                uint4 av[4];
                #pragma unroll
                for (int mi = 0; mi < 4; ++mi)
                    av[mi] = g_Afrag[(((mblk0 + mi) * 4 + j) * 4 + kk) * 32 + lane];
                #pragma unroll
                for (int mi = 0; mi < 4; ++mi) {
                    #pragma unroll
                    for (int nj = 0; nj < 8; ++nj) {
                        uint32_t bb[2];
                        bb[0] = i ? bv[nj].z : bv[nj].x;
                        bb[1] = i ? bv[nj].w : bv[nj].y;
                        mma16816(acc[mi][nj], (const uint32_t*)&av[mi], bb);
                    }
                }
            }
        }
    }

    // ---- fused ArcFace epilogue ----
    const float tn = g_tnew;
    #pragma unroll
    for (int mi = 0; mi < 4; ++mi) {
        int r0 = m0 + wm * 64 + mi * 16 + g;
        #pragma unroll
        for (int half = 0; half < 2; ++half) {
            int brow = r0 + half * 8;
            int tgt   = g_targets[brow];
            float ctm = g_ctm[brow];
            float ftl = g_ftl[brow];
            size_t rowbase = (size_t)brow * C;
            #pragma unroll
            for (int nj = 0; nj < 8; ++nj) {
                int c = n0 + wn * 64 + nj * 8 + tig * 2;
                float v0 = acc[mi][nj][half * 2 + 0];
                float v1 = acc[mi][nj][half * 2 + 1];
                v0 = (v0 > ctm) ? v0 * (tn + v0) : v0;
                v1 = (v1 > ctm) ? v1 * (tn + v1) : v1;
                if (c == tgt)     v0 = ftl;
                if (c + 1 == tgt) v1 = ftl;
                v0 *= S_SCALE;
                v1 *= S_SCALE;
                if (c + 1 < C) {
                    *(float2*)&pred[rowbase + c] = make_float2(v0, v1);
                } else if (c < C) {
                    pred[rowbase + c] = v0;
                }
            }
        }
    }
}

// ---------------- launch ----------------
extern "C" void kernel_launch(void* const* d_in, const int* in_sizes, int n_in,
                              void* d_out, int out_size) {
    const float* features = (const float*)d_in[0];
    const int*   traw     = (const int*)d_in[1];
    const float* weight   = (const float*)d_in[2];
    const float* t_in     = (const float*)d_in[3];

    float* out    = (float*)d_out;
    float* pred   = out;                        // [B, C]
    float* newW   = out + PRED_ELEMS;           // [C, D]
    float* out_t  = out + PRED_ELEMS + W_ELEMS; // [1]
    float* scratch = pred;                      // reuse pred region as segment-sum scratch

    k_unpack_targets<<<1, B>>>(traw);
    k_normalize_tl<<<B, D>>>(features, weight);
    k_pack_A<<<64, 256>>>();
    k_row_params<<<1, B>>>(t_in, out_t);
    k_zero_scratch<<<B, D>>>(scratch);
    k_accumulate<<<B, D>>>(scratch);
    k_weight_update<<<CPAD / 8, 256>>>(weight, scratch, newW);
    k_cleanup<<<1, B>>>();

    dim3 grid(B / 128, CPAD / 256);             // (4, 391), m fastest
    k_gemm_mma<<<grid, 256>>>(pred);
}